// round 12
// baseline (speedup 1.0000x reference)
#include <cuda_runtime.h>
#include <cuda_fp16.h>
#include <cstdint>
#include <math.h>

#define T 2048
#define D 1024
#define H 16
#define DH 64
#define NC 16
#define CS 128
#define GK 1024
#define NSUB 64   // sub-chunks per head (4 per chunk, 32 rows each)

// ---------------- scratch (no allocations allowed) ----------------
__device__ __half g_gate[T*D];
__device__ __half g_qkv[T*3*D];
__device__ __half g_Q[T*D];
__device__ __half g_K[T*D];
__device__ __half g_V[T*D];
__device__ float g_lkv[H*NSUB*DH*DH];
__device__ float g_lks[H*NSUB*DH];
__device__ float g_Spre[H*NC*DH*DH];
__device__ float g_zpre[H*NC*DH];

// fp16 activations and weights (single-rounded)
__device__ __half g_xa[T*D];          // fp16(x)
__device__ __half g_xna[T*D];         // fp16(ln(x))
__device__ __half g_aa[T*D];          // fp16(attn out)
__device__ __half g_qwh[3*D*D];
__device__ __half g_gwh[D*D];
__device__ __half g_pwh[D*D];

// ---------------- helpers ----------------
__device__ __forceinline__ uint32_t smem_u32(const void* p){
  uint32_t a;
  asm("{ .reg .u64 t; cvta.to.shared.u64 t, %1; cvt.u32.u64 %0, t; }" : "=r"(a) : "l"(p));
  return a;
}
__device__ __forceinline__ float elu1f(float x){ return x > 0.f ? x + 1.f : expf(x); }

__device__ __forceinline__ void ldsm_x4(uint32_t* r, uint32_t addr){
  asm volatile("ldmatrix.sync.aligned.m8n8.x4.shared.b16 {%0,%1,%2,%3}, [%4];"
    : "=r"(r[0]), "=r"(r[1]), "=r"(r[2]), "=r"(r[3]) : "r"(addr));
}
__device__ __forceinline__ void mma_f16(float* c, const uint32_t* a, const uint32_t* b){
  asm volatile(
    "mma.sync.aligned.m16n8k16.row.col.f32.f16.f16.f32 "
    "{%0,%1,%2,%3},{%4,%5,%6,%7},{%8,%9},{%0,%1,%2,%3};"
    : "+f"(c[0]), "+f"(c[1]), "+f"(c[2]), "+f"(c[3])
    : "r"(a[0]), "r"(a[1]), "r"(a[2]), "r"(a[3]), "r"(b[0]), "r"(b[1]));
}
__device__ __forceinline__ void cp16(uint32_t smem, const void* gmem){
  asm volatile("cp.async.cg.shared.global [%0], [%1], 16;" :: "r"(smem), "l"(gmem));
}
__device__ __forceinline__ void cp_commit(){
  asm volatile("cp.async.commit_group;" ::: "memory");
}
template<int N>
__device__ __forceinline__ void cp_wait(){
  asm volatile("cp.async.wait_group %0;" :: "n"(N) : "memory");
}

// ---------------- fused split(+LN) kernel ----------------
#define X4 (T*D/4)
#define Q4 (3*D*D/4)
#define G4 (D*D/4)
#define P4 (D*D/4)
#define NB_SPLIT ((X4 + Q4 + G4 + P4) / 256)
__global__ void split_ln_kernel(const float* __restrict__ x, const float* __restrict__ qw,
                                const float* __restrict__ gw, const float* __restrict__ pw,
                                const float* __restrict__ ln_g, const float* __restrict__ ln_b)
{
  if ((int)blockIdx.x < NB_SPLIT){
    int i = blockIdx.x * 256 + threadIdx.x;
    const float* src; __half* hp; int j;
    if (i < X4){ src = x; hp = g_xa; j = i; }
    else if (i < X4 + Q4){ src = qw; hp = g_qwh; j = i - X4; }
    else if (i < X4 + Q4 + G4){ src = gw; hp = g_gwh; j = i - (X4 + Q4); }
    else { src = pw; hp = g_pwh; j = i - (X4 + Q4 + G4); }
    float4 v = ((const float4*)src)[j];
    ((__half2*)hp)[j*2]   = __floats2half2_rn(v.x, v.y);
    ((__half2*)hp)[j*2+1] = __floats2half2_rn(v.z, v.w);
    return;
  }
  __shared__ float red[16];
  const int t = blockIdx.x - NB_SPLIT;
  const int i = threadIdx.x;
  float4 xv = ((const float4*)(x + (size_t)t*D))[i];
  float s  = xv.x + xv.y + xv.z + xv.w;
  float s2 = xv.x*xv.x + xv.y*xv.y + xv.z*xv.z + xv.w*xv.w;
  const int lane = i & 31, w = i >> 5;
  #pragma unroll
  for (int o = 16; o; o >>= 1){
    s  += __shfl_xor_sync(0xffffffffu, s,  o);
    s2 += __shfl_xor_sync(0xffffffffu, s2, o);
  }
  if (lane == 0){ red[w] = s; red[8+w] = s2; }
  __syncthreads();
  if (i == 0){
    float a = 0.f, c = 0.f;
    #pragma unroll
    for (int k = 0; k < 8; k++){ a += red[k]; c += red[8+k]; }
    red[0] = a; red[8] = c;
  }
  __syncthreads();
  const float mu   = red[0] * (1.f / D);
  const float var  = red[8] * (1.f / D) - mu * mu;
  const float rstd = rsqrtf(var + 1e-5f);
  float4 gv = ((const float4*)ln_g)[i];
  float4 bv = ((const float4*)ln_b)[i];
  float o0 = (xv.x - mu) * rstd * gv.x + bv.x;
  float o1 = (xv.y - mu) * rstd * gv.y + bv.y;
  float o2 = (xv.z - mu) * rstd * gv.z + bv.z;
  float o3 = (xv.w - mu) * rstd * gv.w + bv.w;
  const size_t idx4 = ((size_t)t*D >> 2) + i;
  ((__half2*)g_xna)[idx4*2]   = __floats2half2_rn(o0, o1);
  ((__half2*)g_xna)[idx4*2+1] = __floats2half2_rn(o2, o3);
}

// ---------------- HMMA GEMM: C[2048,N] = A[2048,1024] @ B[N,1024]^T ----------------
#define PITCH 80           // bytes per SMEM row (64B data + 16B pad)
#define ARR   (128*PITCH)  // 10240 B per array
#define STAGE (2*ARR)      // A + B = 20480 B
#define NRING 4
#define NKT   (GK/32)      // 32 k-tiles
#define GEMM_SMEM (NRING*STAGE)  // 81920 B

struct GArgs {
  const __half* A;
  const __half* B;
  const float* bias;
  void* C;
  int N;
  int sig;
  int half_out;
};

__device__ __forceinline__ void gemm_load_stage(uint32_t sbase,
    const __half* A, const __half* B, int kt, int tid)
{
  const int koff = kt * 32;
  #pragma unroll
  for (int it = 0; it < 2; it++){
    const int w = tid + it * 256;      // 0..511
    const int row = w >> 2, c16 = w & 3;
    cp16(sbase + row*PITCH + c16*16,       A + (size_t)row * GK + koff + c16*8);
    cp16(sbase + ARR + row*PITCH + c16*16, B + (size_t)row * GK + koff + c16*8);
  }
}

__global__ void __launch_bounds__(256, 2)
hmma_gemm_dual(GArgs g0, GArgs g1, int split)
{
  extern __shared__ __align__(128) char sm[];
  const uint32_t sb = smem_u32(sm);
  const int tid = threadIdx.x;
  const int wid = tid >> 5, lane = tid & 31;
  const int wm = wid & 1, wn = wid >> 1;
  const int m0w = wm * 64, n0w = wn * 32;

  const bool first = ((int)blockIdx.x < split);
  const GArgs ga = first ? g0 : g1;
  const int bxn = first ? (int)blockIdx.x : (int)blockIdx.x - split;
  const int bn0 = bxn << 7, bm0 = blockIdx.y << 7;

  const __half* pA = ga.A + (size_t)bm0 * GK;
  const __half* pB = ga.B + (size_t)bn0 * GK;

  float acc[4][4][4];
  #pragma unroll
  for (int i = 0; i < 4; i++)
    #pragma unroll
    for (int j = 0; j < 4; j++)
      #pragma unroll
      for (int q = 0; q < 4; q++) acc[i][j][q] = 0.f;

  const int rowA = lane & 15;
  const uint32_t colA = (lane >> 4) << 4;
  const int rowB = (lane & 7) + (((lane >> 4) & 1) << 3);
  const uint32_t colB = ((lane >> 3) & 1) << 4;

  gemm_load_stage(sb + 0*STAGE, pA, pB, 0, tid); cp_commit();
  gemm_load_stage(sb + 1*STAGE, pA, pB, 1, tid); cp_commit();
  gemm_load_stage(sb + 2*STAGE, pA, pB, 2, tid); cp_commit();

  for (int kt = 0; kt < NKT; kt++){
    cp_wait<2>();
    __syncthreads();

    if (kt + 3 < NKT)
      gemm_load_stage(sb + ((kt + 3) & (NRING-1)) * STAGE, pA, pB, kt + 3, tid);
    cp_commit();

    const uint32_t st = sb + (kt & (NRING-1)) * STAGE;
    const uint32_t aB = st       + (m0w + rowA) * PITCH + colA;
    const uint32_t bB = st + ARR + (n0w + rowB) * PITCH + colB;

    #pragma unroll
    for (int ks = 0; ks < 2; ks++){
      const uint32_t kb = ks * 32;
      uint32_t a16[4][4], b16[4][2];
      #pragma unroll
      for (int mi = 0; mi < 4; mi++)
        ldsm_x4(a16[mi], aB + mi*16*PITCH + kb);
      #pragma unroll
      for (int p = 0; p < 2; p++){
        uint32_t r[4];
        ldsm_x4(r, bB + p*16*PITCH + kb);
        b16[2*p][0] = r[0]; b16[2*p][1] = r[1];
        b16[2*p+1][0] = r[2]; b16[2*p+1][1] = r[3];
      }
      #pragma unroll
      for (int mi = 0; mi < 4; mi++)
        #pragma unroll
        for (int nj = 0; nj < 4; nj++)
          mma_f16(acc[mi][nj], a16[mi], b16[nj]);
    }
  }

  const int g = lane >> 2, t4 = lane & 3;
  #pragma unroll
  for (int mi = 0; mi < 4; mi++){
    #pragma unroll
    for (int nj = 0; nj < 4; nj++){
      const int row = bm0 + m0w + mi*16 + g;
      const int col = bn0 + n0w + nj*8 + t4*2;
      float b0 = ga.bias[col], b1 = ga.bias[col+1];
      float o0 = acc[mi][nj][0] + b0;
      float o1 = acc[mi][nj][1] + b1;
      float o2 = acc[mi][nj][2] + b0;
      float o3 = acc[mi][nj][3] + b1;
      if (ga.sig){
        o0 = 1.f / (1.f + expf(-o0)); o1 = 1.f / (1.f + expf(-o1));
        o2 = 1.f / (1.f + expf(-o2)); o3 = 1.f / (1.f + expf(-o3));
      }
      if (ga.half_out){
        __half* cp = (__half*)ga.C;
        *(__half2*)(cp + (size_t)row * ga.N + col)       = __floats2half2_rn(o0, o1);
        *(__half2*)(cp + (size_t)(row + 8) * ga.N + col) = __floats2half2_rn(o2, o3);
      } else {
        float* cp = (float*)ga.C;
        *(float2*)(cp + (size_t)row * ga.N + col)       = make_float2(o0, o1);
        *(float2*)(cp + (size_t)(row + 8) * ga.N + col) = make_float2(o2, o3);
      }
    }
  }
}

// ---------------- gate-normalize + apply + elu+1 + head split (fp16 in/out) ----------------
__global__ void prep_kernel(const __half* __restrict__ gate, const __half* __restrict__ qkv,
                            __half* __restrict__ Q, __half* __restrict__ K, __half* __restrict__ V)
{
  __shared__ float red[8];
  const int t = blockIdx.x, i = threadIdx.x;
  const __half2* grow = (const __half2*)(gate + (size_t)t*D);
  __half2 g0 = grow[i*2], g1 = grow[i*2+1];
  float gx = __low2float(g0), gy = __high2float(g0);
  float gz = __low2float(g1), gw2 = __high2float(g1);
  float s = gx + gy + gz + gw2;
  const int lane = i & 31, w = i >> 5;
  #pragma unroll
  for (int o = 16; o; o >>= 1) s += __shfl_xor_sync(0xffffffffu, s, o);
  if (lane == 0) red[w] = s;
  __syncthreads();
  if (i == 0){
    float a = 0.f;
    #pragma unroll
    for (int k = 0; k < 8; k++) a += red[k];
    red[0] = a;
  }
  __syncthreads();
  const float inv = 1.f / (red[0] * (1.f / D) + 1e-5f);

  const __half2* qrow = (const __half2*)(qkv + (size_t)t * 3 * D);
  __half2 q0 = qrow[i*2], q1 = qrow[i*2+1];
  __half2 k0 = qrow[D/2 + i*2], k1 = qrow[D/2 + i*2+1];
  __half2 v0 = qrow[D + i*2],   v1 = qrow[D + i*2+1];

  float qo0 = elu1f(__low2float(q0)  * gx  * inv);
  float qo1 = elu1f(__high2float(q0) * gy  * inv);
  float qo2 = elu1f(__low2float(q1)  * gz  * inv);
  float qo3 = elu1f(__high2float(q1) * gw2 * inv);
  float ko0 = elu1f(__low2float(k0)  * gx  * inv);
  float ko1 = elu1f(__high2float(k0) * gy  * inv);
  float ko2 = elu1f(__low2float(k1)  * gz  * inv);
  float ko3 = elu1f(__high2float(k1) * gw2 * inv);

  const int h = i >> 4;
  const int dh = (i & 15) << 2;
  const size_t base = (size_t)(h * T + t) * DH + dh;
  *(__half2*)(Q + base)     = __floats2half2_rn(qo0, qo1);
  *(__half2*)(Q + base + 2) = __floats2half2_rn(qo2, qo3);
  *(__half2*)(K + base)     = __floats2half2_rn(ko0, ko1);
  *(__half2*)(K + base + 2) = __floats2half2_rn(ko2, ko3);
  *(__half2*)(V + base)     = v0;
  *(__half2*)(V + base + 2) = v1;
}

// ---------------- per-(head,sub-chunk) local K^T V and K column sums ----------------
// grid = H*NSUB (1024 blocks), 32 rows per block; 4x4 register tiles
__global__ void chunk_sums_kernel(const __half* __restrict__ Kg, const __half* __restrict__ Vg,
                                  float* __restrict__ lkv, float* __restrict__ lks)
{
  extern __shared__ float smf[];
  float* Ks = smf;            // 32 x 64
  float* Vs = smf + 32 * DH;  // 32 x 64
  const int b = blockIdx.x;
  const int h = b >> 6, sub = b & 63;
  const int row0 = sub * 32;
  const __half* Kc = Kg + ((size_t)h * T + row0) * DH;
  const __half* Vc = Vg + ((size_t)h * T + row0) * DH;
  const int tid = threadIdx.x;
  #pragma unroll
  for (int it = 0; it < 2; it++){
    const int idx = tid + it * 256;   // 0..511, 4 halves each
    uint2 kq = ((const uint2*)Kc)[idx];
    uint2 vq = ((const uint2*)Vc)[idx];
    __half2 ka = *(__half2*)&kq.x, kb = *(__half2*)&kq.y;
    __half2 va = *(__half2*)&vq.x, vb = *(__half2*)&vq.y;
    float* kd = Ks + idx * 4;
    kd[0] = __low2float(ka); kd[1] = __high2float(ka);
    kd[2] = __low2float(kb); kd[3] = __high2float(kb);
    float* vd = Vs + idx * 4;
    vd[0] = __low2float(va); vd[1] = __high2float(va);
    vd[2] = __low2float(vb); vd[3] = __high2float(vb);
  }
  __syncthreads();

  const int tm = tid & 15, td = tid >> 4;
  const int m0 = tm * 4, d0 = td * 4;
  float acc[4][4];
  #pragma unroll
  for (int i = 0; i < 4; i++)
    #pragma unroll
    for (int j = 0; j < 4; j++) acc[i][j] = 0.f;
  for (int tt = 0; tt < 32; tt++){
    float4 k4 = *(const float4*)&Ks[tt * DH + d0];
    float4 v4 = *(const float4*)&Vs[tt * DH + m0];
    float kk[4] = {k4.x, k4.y, k4.z, k4.w};
    float vv[4] = {v4.x, v4.y, v4.z, v4.w};
    #pragma unroll
    for (int i = 0; i < 4; i++)
      #pragma unroll
      for (int j = 0; j < 4; j++)
        acc[i][j] += kk[i] * vv[j];
  }
  float* dst = lkv + (size_t)b * DH * DH;
  #pragma unroll
  for (int i = 0; i < 4; i++)
    *(float4*)&dst[(d0 + i) * DH + m0] = make_float4(acc[i][0], acc[i][1], acc[i][2], acc[i][3]);

  if (tid < DH){
    float s = 0.f;
    for (int tt = 0; tt < 32; tt++) s += Ks[tt * DH + tid];
    lks[(size_t)b * DH + tid] = s;
  }
}

// ---------------- exclusive prefix over sub-chunks -> per-chunk Spre/zpre ----------------
__global__ void scan_kernel(const float* __restrict__ lkv, const float* __restrict__ lks,
                            float* __restrict__ Spre, float* __restrict__ zpre)
{
  const int h = blockIdx.y;
  const int idx = blockIdx.x * 256 + threadIdx.x;   // 0..4095
  float acc = 0.f;
  #pragma unroll
  for (int s = 0; s < NSUB; s++){
    if (!(s & 3))
      Spre[((size_t)(h * NC + (s >> 2))) * DH * DH + idx] = acc;
    acc += lkv[((size_t)(h * NSUB + s)) * DH * DH + idx];
  }
  if (blockIdx.x == 0 && threadIdx.x < DH){
    const int d = threadIdx.x;
    float a = 0.f;
    #pragma unroll
    for (int s = 0; s < NSUB; s++){
      if (!(s & 3))
        zpre[(h * NC + (s >> 2)) * DH + d] = a;
      a += lks[(h * NSUB + s) * DH + d];
    }
  }
}

// ---------------- per-(head,chunk) attention output -> fp16 (512 threads) ----------------
__global__ void __launch_bounds__(512, 1)
attn_kernel(const __half* __restrict__ Qg, const __half* __restrict__ Kg,
            const __half* __restrict__ Vg, const float* __restrict__ Spre,
            const float* __restrict__ zpre)
{
  extern __shared__ float smf[];
  float* Qs  = smf;              // 128 x 65
  float* Ks  = Qs  + 128 * 65;   // 128 x 65 (later reused for V)
  float* As  = Ks  + 128 * 65;   // 128 x 130
  float* Sp  = As  + 128 * 130;  // 64 x 65
  float* zp  = Sp  + 64 * 65;    // 64
  float* dn  = zp  + 64;         // 128
  float* dnp = dn  + 128;        // 128 x 16

  const int hc = blockIdx.x, h = hc >> 4, c = hc & 15;
  const int tid = threadIdx.x;
  const __half* Qc = Qg + (size_t)(h * T + c * CS) * DH;
  const __half* Kc = Kg + (size_t)(h * T + c * CS) * DH;

  for (int idx = tid; idx < CS * DH / 4; idx += 512){
    const int r = idx >> 4, c4 = (idx & 15) << 2;
    uint2 qq = ((const uint2*)Qc)[idx];
    uint2 kk = ((const uint2*)Kc)[idx];
    __half2 qa = *(__half2*)&qq.x, qb = *(__half2*)&qq.y;
    __half2 ka = *(__half2*)&kk.x, kb = *(__half2*)&kk.y;
    float* qd = Qs + r * 65 + c4;
    qd[0] = __low2float(qa); qd[1] = __high2float(qa);
    qd[2] = __low2float(qb); qd[3] = __high2float(qb);
    float* kd = Ks + r * 65 + c4;
    kd[0] = __low2float(ka); kd[1] = __high2float(ka);
    kd[2] = __low2float(kb); kd[3] = __high2float(kb);
  }
  const float* SpG = Spre + (size_t)hc * DH * DH;
  for (int idx = tid; idx < DH * DH; idx += 512)
    Sp[(idx >> 6) * 65 + (idx & 63)] = SpG[idx];
  if (tid < 64) zp[tid] = zpre[(size_t)hc * DH + tid];
  __syncthreads();

  if (tid < 128){
    float s = 0.f;
    #pragma unroll
    for (int d = 0; d < 64; d++) s += Qs[tid * 65 + d] * zp[d];
    dn[tid] = s;
  }
  __syncthreads();

  const int tx = tid & 15, ty = tid >> 4;   // tx 0..15, ty 0..31
  // phase 1: A = QK^T with causal mask; tiles above diagonal skip
  {
    const int r_hi = ty * 4 + 3;
    if (tx * 8 <= r_hi){
      float acc[4][8];
      #pragma unroll
      for (int i = 0; i < 4; i++)
        #pragma unroll
        for (int j = 0; j < 8; j++) acc[i][j] = 0.f;
      for (int d = 0; d < 64; d++){
        float a[4], b[8];
        #pragma unroll
        for (int i = 0; i < 4; i++) a[i] = Qs[(ty * 4 + i) * 65 + d];
        #pragma unroll
        for (int j = 0; j < 8; j++) b[j] = Ks[(tx * 8 + j) * 65 + d];
        #pragma unroll
        for (int i = 0; i < 4; i++)
          #pragma unroll
          for (int j = 0; j < 8; j++)
            acc[i][j] += a[i] * b[j];
      }
      #pragma unroll
      for (int i = 0; i < 4; i++){
        const int r = ty * 4 + i;
        float rs = 0.f;
        #pragma unroll
        for (int j = 0; j < 8; j++){
          const int s_ = tx * 8 + j;
          const float v = (s_ <= r) ? acc[i][j] : 0.f;
          As[r * 130 + s_] = v;
          rs += v;
        }
        dnp[r * 16 + tx] = rs;
      }
    } else {
      #pragma unroll
      for (int i = 0; i < 4; i++)
        dnp[(ty * 4 + i) * 16 + tx] = 0.f;
    }
  }
  __syncthreads();

  // load V over K buffer; finalize den
  {
    const __half* Vc = Vg + (size_t)(h * T + c * CS) * DH;
    for (int idx = tid; idx < CS * DH / 4; idx += 512){
      const int r = idx >> 4, c4 = (idx & 15) << 2;
      uint2 vv4 = ((const uint2*)Vc)[idx];
      __half2 va = *(__half2*)&vv4.x, vb = *(__half2*)&vv4.y;
      float* vd = Ks + r * 65 + c4;
      vd[0] = __low2float(va); vd[1] = __high2float(va);
      vd[2] = __low2float(vb); vd[3] = __high2float(vb);
    }
    if (tid < 128){
      float s = dn[tid];
      #pragma unroll
      for (int xx = 0; xx < 16; xx++) s += dnp[tid * 16 + xx];
      dn[tid] = s + 1e-5f;
    }
  }
  __syncthreads();

  // phase 2: out = (A@V + Q@Spre)/den; causal loop bound
  {
    float acc2[4][4];
    #pragma unroll
    for (int i = 0; i < 4; i++)
      #pragma unroll
      for (int j = 0; j < 4; j++) acc2[i][j] = 0.f;
    const int m0 = tx * 4, r0 = ty * 4;
    const int send = r0 + 4;
    for (int s = 0; s < send; s++){
      float vv[4];
      #pragma unroll
      for (int jj = 0; jj < 4; jj++) vv[jj] = Ks[s * 65 + m0 + jj];
      #pragma unroll
      for (int i = 0; i < 4; i++){
        const float av = As[(r0 + i) * 130 + s];
        #pragma unroll
        for (int jj = 0; jj < 4; jj++) acc2[i][jj] += av * vv[jj];
      }
    }
    for (int d = 0; d < 64; d++){
      float sp[4];
      #pragma unroll
      for (int jj = 0; jj < 4; jj++) sp[jj] = Sp[d * 65 + m0 + jj];
      #pragma unroll
      for (int i = 0; i < 4; i++){
        const float qv = Qs[(r0 + i) * 65 + d];
        #pragma unroll
        for (int jj = 0; jj < 4; jj++) acc2[i][jj] += qv * sp[jj];
      }
    }
    const size_t obase = (size_t)(c * CS) * D + h * DH;
    #pragma unroll
    for (int i = 0; i < 4; i++){
      const float inv = 1.f / dn[r0 + i];
      const size_t ptr = obase + (size_t)(r0 + i) * D + m0;
      *(__half2*)&g_aa[ptr]     = __floats2half2_rn(acc2[i][0] * inv, acc2[i][1] * inv);
      *(__half2*)&g_aa[ptr + 2] = __floats2half2_rn(acc2[i][2] * inv, acc2[i][3] * inv);
    }
  }
}

// ---------------- launch ----------------
extern "C" void kernel_launch(void* const* d_in, const int* in_sizes, int n_in,
                              void* d_out, int out_size)
{
  (void)in_sizes; (void)n_in; (void)out_size;
  const float* x      = (const float*)d_in[0];
  const float* ln_g   = (const float*)d_in[1];
  const float* ln_b   = (const float*)d_in[2];
  const float* qkv_w  = (const float*)d_in[3];
  const float* qkv_b  = (const float*)d_in[4];
  const float* gate_w = (const float*)d_in[5];
  const float* gate_b = (const float*)d_in[6];
  const float* proj_w = (const float*)d_in[7];
  const float* proj_b = (const float*)d_in[8];
  float* out = (float*)d_out;

  float *lkv, *lks, *Spre, *zpre;
  __half *gate, *qkv, *Q, *K, *V, *xa, *xna, *aa, *qwh, *gwh, *pwh;
  cudaGetSymbolAddress((void**)&gate, g_gate);
  cudaGetSymbolAddress((void**)&qkv,  g_qkv);
  cudaGetSymbolAddress((void**)&Q,    g_Q);
  cudaGetSymbolAddress((void**)&K,    g_K);
  cudaGetSymbolAddress((void**)&V,    g_V);
  cudaGetSymbolAddress((void**)&lkv,  g_lkv);
  cudaGetSymbolAddress((void**)&lks,  g_lks);
  cudaGetSymbolAddress((void**)&Spre, g_Spre);
  cudaGetSymbolAddress((void**)&zpre, g_zpre);
  cudaGetSymbolAddress((void**)&xa,   g_xa);
  cudaGetSymbolAddress((void**)&xna,  g_xna);
  cudaGetSymbolAddress((void**)&aa,   g_aa);
  cudaGetSymbolAddress((void**)&qwh,  g_qwh);
  cudaGetSymbolAddress((void**)&gwh,  g_gwh);
  cudaGetSymbolAddress((void**)&pwh,  g_pwh);

  const int CHUNK_SMEM = 2 * 32 * DH * 4;   // 16384
  const int ATTN_SMEM  = (128*65 + 128*65 + 128*130 + 64*65 + 64 + 128 + 128*16) * 4;
  cudaFuncSetAttribute(chunk_sums_kernel, cudaFuncAttributeMaxDynamicSharedMemorySize, CHUNK_SMEM);
  cudaFuncSetAttribute(attn_kernel,       cudaFuncAttributeMaxDynamicSharedMemorySize, ATTN_SMEM);
  cudaFuncSetAttribute(hmma_gemm_dual,    cudaFuncAttributeMaxDynamicSharedMemorySize, GEMM_SMEM);

  // fused conversions + LayerNorm
  split_ln_kernel<<<NB_SPLIT + T, 256>>>(x, qkv_w, gate_w, proj_w, ln_g, ln_b);

  // gate + qkv single-term fp16 (merged launch), fp16 outputs
  GArgs gateArgs = { xa,  gwh, gate_b, gate, D,     1, 1 };
  GArgs qkvArgs  = { xna, qwh, qkv_b,  qkv,  3 * D, 0, 1 };
  hmma_gemm_dual<<<dim3(8 + 24, T / 128), 256, GEMM_SMEM>>>(gateArgs, qkvArgs, 8);

  prep_kernel<<<T, 256>>>(gate, qkv, Q, K, V);
  chunk_sums_kernel<<<H * NSUB, 256, CHUNK_SMEM>>>(K, V, lkv, lks);
  scan_kernel<<<dim3(16, H), 256>>>(lkv, lks, Spre, zpre);
  attn_kernel<<<H * NC, 512, ATTN_SMEM>>>(Q, K, V, Spre, zpre);

  // proj: single-term fp16, fp32 output
  GArgs projArgs = { aa, pwh, proj_b, out, D, 0, 0 };
  hmma_gemm_dual<<<dim3(8, T / 128), 256, GEMM_SMEM>>>(projArgs, projArgs, 8);
}

// round 13
// speedup vs baseline: 1.0111x; 1.0111x over previous
#include <cuda_runtime.h>
#include <cuda_fp16.h>
#include <cstdint>
#include <math.h>

#define T 2048
#define D 1024
#define H 16
#define DH 64
#define NC 16
#define CS 128
#define GK 1024
#define NSUB 64   // sub-chunks per head (4 per chunk, 32 rows each)

// ---------------- scratch (no allocations allowed) ----------------
__device__ __half g_gate[T*D];
__device__ __half g_qkv[T*3*D];
__device__ __half g_Q[T*D];
__device__ __half g_K[T*D];
__device__ __half g_V[T*D];
__device__ float g_lkv[H*NSUB*DH*DH];
__device__ float g_lks[H*NSUB*DH];
__device__ float g_Spre[H*NC*DH*DH];
__device__ float g_zpre[H*NC*DH];

// fp16 activations and weights (single-rounded)
__device__ __half g_xa[T*D];          // fp16(x)
__device__ __half g_xna[T*D];         // fp16(ln(x))
__device__ __half g_aa[T*D];          // fp16(attn out)
__device__ __half g_qwh[3*D*D];
__device__ __half g_gwh[D*D];
__device__ __half g_pwh[D*D];

// ---------------- helpers ----------------
__device__ __forceinline__ uint32_t smem_u32(const void* p){
  uint32_t a;
  asm("{ .reg .u64 t; cvta.to.shared.u64 t, %1; cvt.u32.u64 %0, t; }" : "=r"(a) : "l"(p));
  return a;
}
__device__ __forceinline__ float elu1f(float x){ return x > 0.f ? x + 1.f : expf(x); }

__device__ __forceinline__ void ldsm_x4(uint32_t* r, uint32_t addr){
  asm volatile("ldmatrix.sync.aligned.m8n8.x4.shared.b16 {%0,%1,%2,%3}, [%4];"
    : "=r"(r[0]), "=r"(r[1]), "=r"(r[2]), "=r"(r[3]) : "r"(addr));
}
__device__ __forceinline__ void mma_f16(float* c, const uint32_t* a, const uint32_t* b){
  asm volatile(
    "mma.sync.aligned.m16n8k16.row.col.f32.f16.f16.f32 "
    "{%0,%1,%2,%3},{%4,%5,%6,%7},{%8,%9},{%0,%1,%2,%3};"
    : "+f"(c[0]), "+f"(c[1]), "+f"(c[2]), "+f"(c[3])
    : "r"(a[0]), "r"(a[1]), "r"(a[2]), "r"(a[3]), "r"(b[0]), "r"(b[1]));
}
__device__ __forceinline__ void cp16(uint32_t smem, const void* gmem){
  asm volatile("cp.async.cg.shared.global [%0], [%1], 16;" :: "r"(smem), "l"(gmem));
}
__device__ __forceinline__ void cp_commit(){
  asm volatile("cp.async.commit_group;" ::: "memory");
}
template<int N>
__device__ __forceinline__ void cp_wait(){
  asm volatile("cp.async.wait_group %0;" :: "n"(N) : "memory");
}

// ---------------- fused split(+LN) kernel ----------------
#define X4 (T*D/4)
#define Q4 (3*D*D/4)
#define G4 (D*D/4)
#define P4 (D*D/4)
#define NB_SPLIT ((X4 + Q4 + G4 + P4) / 256)
__global__ void split_ln_kernel(const float* __restrict__ x, const float* __restrict__ qw,
                                const float* __restrict__ gw, const float* __restrict__ pw,
                                const float* __restrict__ ln_g, const float* __restrict__ ln_b)
{
  if ((int)blockIdx.x < NB_SPLIT){
    int i = blockIdx.x * 256 + threadIdx.x;
    const float* src; __half* hp; int j;
    if (i < X4){ src = x; hp = g_xa; j = i; }
    else if (i < X4 + Q4){ src = qw; hp = g_qwh; j = i - X4; }
    else if (i < X4 + Q4 + G4){ src = gw; hp = g_gwh; j = i - (X4 + Q4); }
    else { src = pw; hp = g_pwh; j = i - (X4 + Q4 + G4); }
    float4 v = ((const float4*)src)[j];
    ((__half2*)hp)[j*2]   = __floats2half2_rn(v.x, v.y);
    ((__half2*)hp)[j*2+1] = __floats2half2_rn(v.z, v.w);
    return;
  }
  __shared__ float red[16];
  const int t = blockIdx.x - NB_SPLIT;
  const int i = threadIdx.x;
  float4 xv = ((const float4*)(x + (size_t)t*D))[i];
  float s  = xv.x + xv.y + xv.z + xv.w;
  float s2 = xv.x*xv.x + xv.y*xv.y + xv.z*xv.z + xv.w*xv.w;
  const int lane = i & 31, w = i >> 5;
  #pragma unroll
  for (int o = 16; o; o >>= 1){
    s  += __shfl_xor_sync(0xffffffffu, s,  o);
    s2 += __shfl_xor_sync(0xffffffffu, s2, o);
  }
  if (lane == 0){ red[w] = s; red[8+w] = s2; }
  __syncthreads();
  if (i == 0){
    float a = 0.f, c = 0.f;
    #pragma unroll
    for (int k = 0; k < 8; k++){ a += red[k]; c += red[8+k]; }
    red[0] = a; red[8] = c;
  }
  __syncthreads();
  const float mu   = red[0] * (1.f / D);
  const float var  = red[8] * (1.f / D) - mu * mu;
  const float rstd = rsqrtf(var + 1e-5f);
  float4 gv = ((const float4*)ln_g)[i];
  float4 bv = ((const float4*)ln_b)[i];
  float o0 = (xv.x - mu) * rstd * gv.x + bv.x;
  float o1 = (xv.y - mu) * rstd * gv.y + bv.y;
  float o2 = (xv.z - mu) * rstd * gv.z + bv.z;
  float o3 = (xv.w - mu) * rstd * gv.w + bv.w;
  const size_t idx4 = ((size_t)t*D >> 2) + i;
  ((__half2*)g_xna)[idx4*2]   = __floats2half2_rn(o0, o1);
  ((__half2*)g_xna)[idx4*2+1] = __floats2half2_rn(o2, o3);
}

// ---------------- HMMA GEMM: C[M,N] = A[M,1024] @ B[N,1024]^T ----------------
// BM-templated block tile (BM x 128), BK=32, 8 warps, 4-stage cp.async ring.
#define PITCH 80           // bytes per SMEM row (64B data + 16B pad)
#define ARR   (128*PITCH)  // B array: 10240 B
#define NRING 4
#define NKT   (GK/32)      // 32 k-tiles

struct GArgs {
  const __half* A;
  const __half* B;
  const float* bias;
  void* C;
  int N;
  int sig;
  int half_out;
};

template<int BM>
__device__ __forceinline__ void gemm_load_stage(uint32_t sbase,
    const __half* A, const __half* B, int kt, int tid)
{
  constexpr int ARR_A = BM * PITCH;
  const int koff = kt * 32;
  #pragma unroll
  for (int i = tid; i < BM*4; i += 256){
    const int row = i >> 2, c16 = i & 3;
    cp16(sbase + row*PITCH + c16*16, A + (size_t)row * GK + koff + c16*8);
  }
  #pragma unroll
  for (int i = tid; i < 512; i += 256){
    const int row = i >> 2, c16 = i & 3;
    cp16(sbase + ARR_A + row*PITCH + c16*16, B + (size_t)row * GK + koff + c16*8);
  }
}

template<int BM>
__global__ void __launch_bounds__(256, 2)
hmma_gemm_dual(GArgs g0, GArgs g1, int split)
{
  constexpr int MI = BM / 32;          // mi tiles per warp
  constexpr int ARR_A = BM * PITCH;
  constexpr int STG = ARR_A + ARR;     // bytes per stage
  extern __shared__ __align__(128) char sm[];
  const uint32_t sb = smem_u32(sm);
  const int tid = threadIdx.x;
  const int wid = tid >> 5, lane = tid & 31;
  const int wm = wid & 1, wn = wid >> 1;
  const int m0w = wm * (BM/2), n0w = wn * 32;

  const bool first = ((int)blockIdx.x < split);
  const GArgs ga = first ? g0 : g1;
  const int bxn = first ? (int)blockIdx.x : (int)blockIdx.x - split;
  const int bn0 = bxn << 7, bm0 = blockIdx.y * BM;

  const __half* pA = ga.A + (size_t)bm0 * GK;
  const __half* pB = ga.B + (size_t)bn0 * GK;

  float acc[MI][4][4];
  #pragma unroll
  for (int i = 0; i < MI; i++)
    #pragma unroll
    for (int j = 0; j < 4; j++)
      #pragma unroll
      for (int q = 0; q < 4; q++) acc[i][j][q] = 0.f;

  const int rowA = lane & 15;
  const uint32_t colA = (lane >> 4) << 4;
  const int rowB = (lane & 7) + (((lane >> 4) & 1) << 3);
  const uint32_t colB = ((lane >> 3) & 1) << 4;

  gemm_load_stage<BM>(sb + 0*STG, pA, pB, 0, tid); cp_commit();
  gemm_load_stage<BM>(sb + 1*STG, pA, pB, 1, tid); cp_commit();
  gemm_load_stage<BM>(sb + 2*STG, pA, pB, 2, tid); cp_commit();

  for (int kt = 0; kt < NKT; kt++){
    cp_wait<2>();
    __syncthreads();

    if (kt + 3 < NKT)
      gemm_load_stage<BM>(sb + ((kt + 3) & (NRING-1)) * STG, pA, pB, kt + 3, tid);
    cp_commit();

    const uint32_t st = sb + (kt & (NRING-1)) * STG;
    const uint32_t aB = st         + (m0w + rowA) * PITCH + colA;
    const uint32_t bB = st + ARR_A + (n0w + rowB) * PITCH + colB;

    #pragma unroll
    for (int ks = 0; ks < 2; ks++){
      const uint32_t kb = ks * 32;
      uint32_t a16[MI][4], b16[4][2];
      #pragma unroll
      for (int mi = 0; mi < MI; mi++)
        ldsm_x4(a16[mi], aB + mi*16*PITCH + kb);
      #pragma unroll
      for (int p = 0; p < 2; p++){
        uint32_t r[4];
        ldsm_x4(r, bB + p*16*PITCH + kb);
        b16[2*p][0] = r[0]; b16[2*p][1] = r[1];
        b16[2*p+1][0] = r[2]; b16[2*p+1][1] = r[3];
      }
      #pragma unroll
      for (int mi = 0; mi < MI; mi++)
        #pragma unroll
        for (int nj = 0; nj < 4; nj++)
          mma_f16(acc[mi][nj], a16[mi], b16[nj]);
    }
  }

  const int g = lane >> 2, t4 = lane & 3;
  #pragma unroll
  for (int mi = 0; mi < MI; mi++){
    #pragma unroll
    for (int nj = 0; nj < 4; nj++){
      const int row = bm0 + m0w + mi*16 + g;
      const int col = bn0 + n0w + nj*8 + t4*2;
      float b0 = ga.bias[col], b1 = ga.bias[col+1];
      float o0 = acc[mi][nj][0] + b0;
      float o1 = acc[mi][nj][1] + b1;
      float o2 = acc[mi][nj][2] + b0;
      float o3 = acc[mi][nj][3] + b1;
      if (ga.sig){
        o0 = 1.f / (1.f + expf(-o0)); o1 = 1.f / (1.f + expf(-o1));
        o2 = 1.f / (1.f + expf(-o2)); o3 = 1.f / (1.f + expf(-o3));
      }
      if (ga.half_out){
        __half* cp = (__half*)ga.C;
        *(__half2*)(cp + (size_t)row * ga.N + col)       = __floats2half2_rn(o0, o1);
        *(__half2*)(cp + (size_t)(row + 8) * ga.N + col) = __floats2half2_rn(o2, o3);
      } else {
        float* cp = (float*)ga.C;
        *(float2*)(cp + (size_t)row * ga.N + col)       = make_float2(o0, o1);
        *(float2*)(cp + (size_t)(row + 8) * ga.N + col) = make_float2(o2, o3);
      }
    }
  }
}

// ---------------- gate-normalize + apply + elu+1 + head split (fp16 in/out) ----------------
__global__ void prep_kernel(const __half* __restrict__ gate, const __half* __restrict__ qkv,
                            __half* __restrict__ Q, __half* __restrict__ K, __half* __restrict__ V)
{
  __shared__ float red[8];
  const int t = blockIdx.x, i = threadIdx.x;
  const __half2* grow = (const __half2*)(gate + (size_t)t*D);
  __half2 g0 = grow[i*2], g1 = grow[i*2+1];
  float gx = __low2float(g0), gy = __high2float(g0);
  float gz = __low2float(g1), gw2 = __high2float(g1);
  float s = gx + gy + gz + gw2;
  const int lane = i & 31, w = i >> 5;
  #pragma unroll
  for (int o = 16; o; o >>= 1) s += __shfl_xor_sync(0xffffffffu, s, o);
  if (lane == 0) red[w] = s;
  __syncthreads();
  if (i == 0){
    float a = 0.f;
    #pragma unroll
    for (int k = 0; k < 8; k++) a += red[k];
    red[0] = a;
  }
  __syncthreads();
  const float inv = 1.f / (red[0] * (1.f / D) + 1e-5f);

  const __half2* qrow = (const __half2*)(qkv + (size_t)t * 3 * D);
  __half2 q0 = qrow[i*2], q1 = qrow[i*2+1];
  __half2 k0 = qrow[D/2 + i*2], k1 = qrow[D/2 + i*2+1];
  __half2 v0 = qrow[D + i*2],   v1 = qrow[D + i*2+1];

  float qo0 = elu1f(__low2float(q0)  * gx  * inv);
  float qo1 = elu1f(__high2float(q0) * gy  * inv);
  float qo2 = elu1f(__low2float(q1)  * gz  * inv);
  float qo3 = elu1f(__high2float(q1) * gw2 * inv);
  float ko0 = elu1f(__low2float(k0)  * gx  * inv);
  float ko1 = elu1f(__high2float(k0) * gy  * inv);
  float ko2 = elu1f(__low2float(k1)  * gz  * inv);
  float ko3 = elu1f(__high2float(k1) * gw2 * inv);

  const int h = i >> 4;
  const int dh = (i & 15) << 2;
  const size_t base = (size_t)(h * T + t) * DH + dh;
  *(__half2*)(Q + base)     = __floats2half2_rn(qo0, qo1);
  *(__half2*)(Q + base + 2) = __floats2half2_rn(qo2, qo3);
  *(__half2*)(K + base)     = __floats2half2_rn(ko0, ko1);
  *(__half2*)(K + base + 2) = __floats2half2_rn(ko2, ko3);
  *(__half2*)(V + base)     = v0;
  *(__half2*)(V + base + 2) = v1;
}

// ---------------- per-(head,sub-chunk) local K^T V and K column sums ----------------
// grid = H*NSUB (1024 blocks), 128 threads; 4x8 register tiles
__global__ void chunk_sums_kernel(const __half* __restrict__ Kg, const __half* __restrict__ Vg,
                                  float* __restrict__ lkv, float* __restrict__ lks)
{
  extern __shared__ float smf[];
  float* Ks = smf;            // 32 x 64
  float* Vs = smf + 32 * DH;  // 32 x 64
  const int b = blockIdx.x;
  const int h = b >> 6, sub = b & 63;
  const int row0 = sub * 32;
  const __half* Kc = Kg + ((size_t)h * T + row0) * DH;
  const __half* Vc = Vg + ((size_t)h * T + row0) * DH;
  const int tid = threadIdx.x;   // 0..127
  #pragma unroll
  for (int it = 0; it < 4; it++){
    const int idx = tid + it * 128;   // 0..511, 4 halves each
    uint2 kq = ((const uint2*)Kc)[idx];
    uint2 vq = ((const uint2*)Vc)[idx];
    __half2 ka = *(__half2*)&kq.x, kb = *(__half2*)&kq.y;
    __half2 va = *(__half2*)&vq.x, vb = *(__half2*)&vq.y;
    float* kd = Ks + idx * 4;
    kd[0] = __low2float(ka); kd[1] = __high2float(ka);
    kd[2] = __low2float(kb); kd[3] = __high2float(kb);
    float* vd = Vs + idx * 4;
    vd[0] = __low2float(va); vd[1] = __high2float(va);
    vd[2] = __low2float(vb); vd[3] = __high2float(vb);
  }
  __syncthreads();

  // thread (tm, td): 4 d-rows x 8 m-cols tile of the 64x64 K^T V
  const int tm = tid & 7, td = tid >> 3;   // tm 0..7, td 0..15
  const int m0 = tm * 8, d0 = td * 4;
  float acc[4][8];
  #pragma unroll
  for (int i = 0; i < 4; i++)
    #pragma unroll
    for (int j = 0; j < 8; j++) acc[i][j] = 0.f;
  for (int tt = 0; tt < 32; tt++){
    float4 k4 = *(const float4*)&Ks[tt * DH + d0];
    float4 va = *(const float4*)&Vs[tt * DH + m0];
    float4 vb = *(const float4*)&Vs[tt * DH + m0 + 4];
    float kk[4] = {k4.x, k4.y, k4.z, k4.w};
    float vv[8] = {va.x, va.y, va.z, va.w, vb.x, vb.y, vb.z, vb.w};
    #pragma unroll
    for (int i = 0; i < 4; i++)
      #pragma unroll
      for (int j = 0; j < 8; j++)
        acc[i][j] += kk[i] * vv[j];
  }
  float* dst = lkv + (size_t)b * DH * DH;
  #pragma unroll
  for (int i = 0; i < 4; i++){
    *(float4*)&dst[(d0 + i) * DH + m0]     = make_float4(acc[i][0], acc[i][1], acc[i][2], acc[i][3]);
    *(float4*)&dst[(d0 + i) * DH + m0 + 4] = make_float4(acc[i][4], acc[i][5], acc[i][6], acc[i][7]);
  }

  if (tid < DH){
    float s = 0.f;
    for (int tt = 0; tt < 32; tt++) s += Ks[tt * DH + tid];
    lks[(size_t)b * DH + tid] = s;
  }
}

// ---------------- exclusive prefix over sub-chunks -> per-chunk Spre/zpre ----------------
__global__ void scan_kernel(const float* __restrict__ lkv, const float* __restrict__ lks,
                            float* __restrict__ Spre, float* __restrict__ zpre)
{
  const int h = blockIdx.y;
  const int idx = blockIdx.x * 256 + threadIdx.x;   // 0..4095
  float acc = 0.f;
  #pragma unroll
  for (int s = 0; s < NSUB; s++){
    if (!(s & 3))
      Spre[((size_t)(h * NC + (s >> 2))) * DH * DH + idx] = acc;
    acc += lkv[((size_t)(h * NSUB + s)) * DH * DH + idx];
  }
  if (blockIdx.x == 0 && threadIdx.x < DH){
    const int d = threadIdx.x;
    float a = 0.f;
    #pragma unroll
    for (int s = 0; s < NSUB; s++){
      if (!(s & 3))
        zpre[(h * NC + (s >> 2)) * DH + d] = a;
      a += lks[(h * NSUB + s) * DH + d];
    }
  }
}

// ---------------- per-(head,chunk) attention output -> fp16 (512 threads) ----------------
__global__ void __launch_bounds__(512, 1)
attn_kernel(const __half* __restrict__ Qg, const __half* __restrict__ Kg,
            const __half* __restrict__ Vg, const float* __restrict__ Spre,
            const float* __restrict__ zpre)
{
  extern __shared__ float smf[];
  float* Qs  = smf;              // 128 x 65
  float* Ks  = Qs  + 128 * 65;   // 128 x 65 (later reused for V)
  float* As  = Ks  + 128 * 65;   // 128 x 130
  float* Sp  = As  + 128 * 130;  // 64 x 65
  float* zp  = Sp  + 64 * 65;    // 64
  float* dn  = zp  + 64;         // 128
  float* dnp = dn  + 128;        // 128 x 16

  const int hc = blockIdx.x, h = hc >> 4, c = hc & 15;
  const int tid = threadIdx.x;
  const __half* Qc = Qg + (size_t)(h * T + c * CS) * DH;
  const __half* Kc = Kg + (size_t)(h * T + c * CS) * DH;

  for (int idx = tid; idx < CS * DH / 4; idx += 512){
    const int r = idx >> 4, c4 = (idx & 15) << 2;
    uint2 qq = ((const uint2*)Qc)[idx];
    uint2 kk = ((const uint2*)Kc)[idx];
    __half2 qa = *(__half2*)&qq.x, qb = *(__half2*)&qq.y;
    __half2 ka = *(__half2*)&kk.x, kb = *(__half2*)&kk.y;
    float* qd = Qs + r * 65 + c4;
    qd[0] = __low2float(qa); qd[1] = __high2float(qa);
    qd[2] = __low2float(qb); qd[3] = __high2float(qb);
    float* kd = Ks + r * 65 + c4;
    kd[0] = __low2float(ka); kd[1] = __high2float(ka);
    kd[2] = __low2float(kb); kd[3] = __high2float(kb);
  }
  const float* SpG = Spre + (size_t)hc * DH * DH;
  for (int idx = tid; idx < DH * DH; idx += 512)
    Sp[(idx >> 6) * 65 + (idx & 63)] = SpG[idx];
  if (tid < 64) zp[tid] = zpre[(size_t)hc * DH + tid];
  __syncthreads();

  if (tid < 128){
    float s = 0.f;
    #pragma unroll
    for (int d = 0; d < 64; d++) s += Qs[tid * 65 + d] * zp[d];
    dn[tid] = s;
  }
  __syncthreads();

  const int tx = tid & 15, ty = tid >> 4;   // tx 0..15, ty 0..31
  // phase 1: A = QK^T with causal mask; tiles above diagonal skip
  {
    const int r_hi = ty * 4 + 3;
    if (tx * 8 <= r_hi){
      float acc[4][8];
      #pragma unroll
      for (int i = 0; i < 4; i++)
        #pragma unroll
        for (int j = 0; j < 8; j++) acc[i][j] = 0.f;
      for (int d = 0; d < 64; d++){
        float a[4], b[8];
        #pragma unroll
        for (int i = 0; i < 4; i++) a[i] = Qs[(ty * 4 + i) * 65 + d];
        #pragma unroll
        for (int j = 0; j < 8; j++) b[j] = Ks[(tx * 8 + j) * 65 + d];
        #pragma unroll
        for (int i = 0; i < 4; i++)
          #pragma unroll
          for (int j = 0; j < 8; j++)
            acc[i][j] += a[i] * b[j];
      }
      #pragma unroll
      for (int i = 0; i < 4; i++){
        const int r = ty * 4 + i;
        float rs = 0.f;
        #pragma unroll
        for (int j = 0; j < 8; j++){
          const int s_ = tx * 8 + j;
          const float v = (s_ <= r) ? acc[i][j] : 0.f;
          As[r * 130 + s_] = v;
          rs += v;
        }
        dnp[r * 16 + tx] = rs;
      }
    } else {
      #pragma unroll
      for (int i = 0; i < 4; i++)
        dnp[(ty * 4 + i) * 16 + tx] = 0.f;
    }
  }
  __syncthreads();

  // load V over K buffer; finalize den
  {
    const __half* Vc = Vg + (size_t)(h * T + c * CS) * DH;
    for (int idx = tid; idx < CS * DH / 4; idx += 512){
      const int r = idx >> 4, c4 = (idx & 15) << 2;
      uint2 vv4 = ((const uint2*)Vc)[idx];
      __half2 va = *(__half2*)&vv4.x, vb = *(__half2*)&vv4.y;
      float* vd = Ks + r * 65 + c4;
      vd[0] = __low2float(va); vd[1] = __high2float(va);
      vd[2] = __low2float(vb); vd[3] = __high2float(vb);
    }
    if (tid < 128){
      float s = dn[tid];
      #pragma unroll
      for (int xx = 0; xx < 16; xx++) s += dnp[tid * 16 + xx];
      dn[tid] = s + 1e-5f;
    }
  }
  __syncthreads();

  // phase 2: out = (A@V + Q@Spre)/den; causal loop bound
  {
    float acc2[4][4];
    #pragma unroll
    for (int i = 0; i < 4; i++)
      #pragma unroll
      for (int j = 0; j < 4; j++) acc2[i][j] = 0.f;
    const int m0 = tx * 4, r0 = ty * 4;
    const int send = r0 + 4;
    for (int s = 0; s < send; s++){
      float vv[4];
      #pragma unroll
      for (int jj = 0; jj < 4; jj++) vv[jj] = Ks[s * 65 + m0 + jj];
      #pragma unroll
      for (int i = 0; i < 4; i++){
        const float av = As[(r0 + i) * 130 + s];
        #pragma unroll
        for (int jj = 0; jj < 4; jj++) acc2[i][jj] += av * vv[jj];
      }
    }
    for (int d = 0; d < 64; d++){
      float sp[4];
      #pragma unroll
      for (int jj = 0; jj < 4; jj++) sp[jj] = Sp[d * 65 + m0 + jj];
      #pragma unroll
      for (int i = 0; i < 4; i++){
        const float qv = Qs[(r0 + i) * 65 + d];
        #pragma unroll
        for (int jj = 0; jj < 4; jj++) acc2[i][jj] += qv * sp[jj];
      }
    }
    const size_t obase = (size_t)(c * CS) * D + h * DH;
    #pragma unroll
    for (int i = 0; i < 4; i++){
      const float inv = 1.f / dn[r0 + i];
      const size_t ptr = obase + (size_t)(r0 + i) * D + m0;
      *(__half2*)&g_aa[ptr]     = __floats2half2_rn(acc2[i][0] * inv, acc2[i][1] * inv);
      *(__half2*)&g_aa[ptr + 2] = __floats2half2_rn(acc2[i][2] * inv, acc2[i][3] * inv);
    }
  }
}

// ---------------- launch ----------------
extern "C" void kernel_launch(void* const* d_in, const int* in_sizes, int n_in,
                              void* d_out, int out_size)
{
  (void)in_sizes; (void)n_in; (void)out_size;
  const float* x      = (const float*)d_in[0];
  const float* ln_g   = (const float*)d_in[1];
  const float* ln_b   = (const float*)d_in[2];
  const float* qkv_w  = (const float*)d_in[3];
  const float* qkv_b  = (const float*)d_in[4];
  const float* gate_w = (const float*)d_in[5];
  const float* gate_b = (const float*)d_in[6];
  const float* proj_w = (const float*)d_in[7];
  const float* proj_b = (const float*)d_in[8];
  float* out = (float*)d_out;

  float *lkv, *lks, *Spre, *zpre;
  __half *gate, *qkv, *Q, *K, *V, *xa, *xna, *aa, *qwh, *gwh, *pwh;
  cudaGetSymbolAddress((void**)&gate, g_gate);
  cudaGetSymbolAddress((void**)&qkv,  g_qkv);
  cudaGetSymbolAddress((void**)&Q,    g_Q);
  cudaGetSymbolAddress((void**)&K,    g_K);
  cudaGetSymbolAddress((void**)&V,    g_V);
  cudaGetSymbolAddress((void**)&lkv,  g_lkv);
  cudaGetSymbolAddress((void**)&lks,  g_lks);
  cudaGetSymbolAddress((void**)&Spre, g_Spre);
  cudaGetSymbolAddress((void**)&zpre, g_zpre);
  cudaGetSymbolAddress((void**)&xa,   g_xa);
  cudaGetSymbolAddress((void**)&xna,  g_xna);
  cudaGetSymbolAddress((void**)&aa,   g_aa);
  cudaGetSymbolAddress((void**)&qwh,  g_qwh);
  cudaGetSymbolAddress((void**)&gwh,  g_gwh);
  cudaGetSymbolAddress((void**)&pwh,  g_pwh);

  const int CHUNK_SMEM  = 2 * 32 * DH * 4;   // 16384
  const int ATTN_SMEM   = (128*65 + 128*65 + 128*130 + 64*65 + 64 + 128 + 128*16) * 4;
  const int GEMM_SMEM128 = NRING * (128*PITCH + ARR);  // 81920
  const int GEMM_SMEM64  = NRING * (64*PITCH + ARR);   // 61440
  cudaFuncSetAttribute(chunk_sums_kernel,  cudaFuncAttributeMaxDynamicSharedMemorySize, CHUNK_SMEM);
  cudaFuncSetAttribute(attn_kernel,        cudaFuncAttributeMaxDynamicSharedMemorySize, ATTN_SMEM);
  cudaFuncSetAttribute(hmma_gemm_dual<128>, cudaFuncAttributeMaxDynamicSharedMemorySize, GEMM_SMEM128);
  cudaFuncSetAttribute(hmma_gemm_dual<64>,  cudaFuncAttributeMaxDynamicSharedMemorySize, GEMM_SMEM64);

  // fused conversions + LayerNorm
  split_ln_kernel<<<NB_SPLIT + T, 256>>>(x, qkv_w, gate_w, proj_w, ln_g, ln_b);

  // gate + qkv single-term fp16 (merged launch), fp16 outputs, BM=128
  GArgs gateArgs = { xa,  gwh, gate_b, gate, D,     1, 1 };
  GArgs qkvArgs  = { xna, qwh, qkv_b,  qkv,  3 * D, 0, 1 };
  hmma_gemm_dual<128><<<dim3(8 + 24, T / 128), 256, GEMM_SMEM128>>>(gateArgs, qkvArgs, 8);

  prep_kernel<<<T, 256>>>(gate, qkv, Q, K, V);
  chunk_sums_kernel<<<H * NSUB, 128, CHUNK_SMEM>>>(K, V, lkv, lks);
  scan_kernel<<<dim3(16, H), 256>>>(lkv, lks, Spre, zpre);
  attn_kernel<<<H * NC, 512, ATTN_SMEM>>>(Q, K, V, Spre, zpre);

  // proj: single-term fp16, fp32 output, BM=64 (256 CTAs -> better chip fill)
  GArgs projArgs = { aa, pwh, proj_b, out, D, 0, 0 };
  hmma_gemm_dual<64><<<dim3(8, T / 64), 256, GEMM_SMEM64>>>(projArgs, projArgs, 8);
}